// round 15
// baseline (speedup 1.0000x reference)
#include <cuda_runtime.h>
#include <cuda_bf16.h>
#include <cstdint>

#define NN   100000
#define DD   100
#define KK   100
#define LL   3
#define NNZS 1600000

#define ND (NN*DD)
#define KD (KK*DD)

// ---------------- device scratch ----------------
__device__ float g_sp [ND];       // spmm output (pre-W)
__device__ float g_xl [LL][ND];
__device__ float g_xsl[LL][ND];
__device__ float g_H1 [NN*KK];
__device__ float g_hh [LL][KD];
__device__ float g_inv1[LL][NN];
__device__ float g_inv2[LL][NN];
__device__ int   g_cnt   [NN];
__device__ int   g_rowptr[NN+1];
__device__ int   g_cursor[NN];
__device__ int   g_cols2 [NNZS];
__device__ float g_vals2 [NNZS];
__device__ int   g_bsums [128];
__device__ int   g_outer_done = 0;
// B in mma fragment order: idx = (ks*13+nc)*32+lane -> uint4{bh0,bh1,bl0,bl1}
// slots: 0..2 = W_item[l], 3 = W_i1, 4 = W_i2, 5 = h (per layer)
__device__ uint4 g_Bf[6][2912];

// ---------------- small utility kernels ----------------
__global__ void k_zerof(float* __restrict__ p, int n) {
    int i = blockIdx.x * blockDim.x + threadIdx.x;
    if (i < n) p[i] = 0.f;
}
__global__ void k_zeroi(int* __restrict__ p, int n) {
    int i = blockIdx.x * blockDim.x + threadIdx.x;
    if (i < n) p[i] = 0;
}

__device__ __forceinline__ void split2(float a, float b, uint32_t& hi, uint32_t& lo) {
    __nv_bfloat16 ah = __float2bfloat16(a), bh = __float2bfloat16(b);
    float ar = a - __bfloat162float(ah);
    float br = b - __bfloat162float(bh);
    __nv_bfloat16 al = __float2bfloat16(ar), bl = __float2bfloat16(br);
    hi = (uint32_t)__bfloat16_as_ushort(ah) | ((uint32_t)__bfloat16_as_ushort(bh) << 16);
    lo = (uint32_t)__bfloat16_as_ushort(al) | ((uint32_t)__bfloat16_as_ushort(bl) << 16);
}
__device__ __forceinline__ float recon2(uint32_t h, uint32_t l, int which) {
    uint16_t hb = which ? (uint16_t)(h >> 16) : (uint16_t)(h & 0xffff);
    uint16_t lb = which ? (uint16_t)(l >> 16) : (uint16_t)(l & 0xffff);
    return __bfloat162float(__ushort_as_bfloat16(hb)) + __bfloat162float(__ushort_as_bfloat16(lb));
}

// ---------------- weight prep into fragment order ----------------
__device__ __forceinline__ void prep_frag(const float* __restrict__ S, int slot, int tid, int nthr) {
    for (int idx = tid; idx < 2912; idx += nthr) {
        int ks = idx / 416;
        int rem = idx - ks * 416;
        int nc = rem >> 5, lane = rem & 31;
        int g = lane >> 2, tp = lane & 3;
        int n = nc * 8 + g;
        int ka = ks * 16 + tp * 2;
        int kb = ka + 8;
        float wa0 = (n < 100 && ka     < 100) ? S[ka * 100 + n]       : 0.f;
        float wa1 = (n < 100 && ka + 1 < 100) ? S[(ka + 1) * 100 + n] : 0.f;
        float wb0 = (n < 100 && kb     < 100) ? S[kb * 100 + n]       : 0.f;
        float wb1 = (n < 100 && kb + 1 < 100) ? S[(kb + 1) * 100 + n] : 0.f;
        uint32_t h0, l0, h1, l1;
        split2(wa0, wa1, h0, l0);
        split2(wb0, wb1, h1, l1);
        g_Bf[slot][idx] = make_uint4(h0, h1, l0, l1);
    }
}
__global__ void k_prep5(const float* __restrict__ W_item, const float* __restrict__ W_i1,
                        const float* __restrict__ W_i2) {
    int b = blockIdx.x;
    const float* S = (b < 3) ? (W_item + b * 10000) : ((b == 3) ? W_i1 : W_i2);
    prep_frag(S, b, threadIdx.x, blockDim.x);
}

// ---------------- CSR build ----------------
__global__ void k_hist(const int* __restrict__ rows) {
    for (int e = blockIdx.x * blockDim.x + threadIdx.x; e < NNZS; e += gridDim.x * blockDim.x)
        atomicAdd(&g_cnt[rows[e]], 1);
}

#define NB_SCAN ((NN + 1023) / 1024)

__global__ void k_scan1() {
    __shared__ int s[1024];
    int tid = threadIdx.x;
    int i = blockIdx.x * 1024 + tid;
    int v = (i < NN) ? g_cnt[i] : 0;
    s[tid] = v;
    __syncthreads();
    for (int off = 1; off < 1024; off <<= 1) {
        int t = 0;
        if (tid >= off) t = s[tid - off];
        __syncthreads();
        if (tid >= off) s[tid] += t;
        __syncthreads();
    }
    if (i < NN) g_rowptr[i] = s[tid] - v;
    if (tid == 0) g_bsums[blockIdx.x] = s[1023];
}
__global__ void k_scan2() {
    int run = 0;
    for (int b = 0; b < NB_SCAN; b++) { int v = g_bsums[b]; g_bsums[b] = run; run += v; }
}
__global__ void k_scan3() {
    int i = blockIdx.x * blockDim.x + threadIdx.x;
    if (i < NN) {
        int v = g_rowptr[i] + g_bsums[i >> 10];
        g_rowptr[i] = v;
        g_cursor[i] = v;
    }
    if (i == 0) g_rowptr[NN] = NNZS;
}
__global__ void k_scatter(const int* __restrict__ rows, const int* __restrict__ cols,
                          const float* __restrict__ vals) {
    for (int e = blockIdx.x * blockDim.x + threadIdx.x; e < NNZS; e += gridDim.x * blockDim.x) {
        int r = rows[e];
        int p = atomicAdd(&g_cursor[r], 1);
        g_cols2[p] = cols[e];
        g_vals2[p] = vals[e];
    }
}

// ---------------- SpMM (warp per row, float4, permuted CSR, 2-edge unroll) ----------------
__global__ void k_spmm(const float* __restrict__ T, float* __restrict__ Out) {
    int warp = (blockIdx.x * blockDim.x + threadIdx.x) >> 5;
    int lane = threadIdx.x & 31;
    if (warp >= NN) return;
    int s = g_rowptr[warp], e = g_rowptr[warp + 1];
    float4 acc = make_float4(0.f, 0.f, 0.f, 0.f);
    int p = s;
    for (; p + 1 < e; p += 2) {
        int c0 = g_cols2[p], c1 = g_cols2[p + 1];
        float v0 = g_vals2[p], v1 = g_vals2[p + 1];
        if (lane < 25) {
            const float4 t0 = *(const float4*)(T + (size_t)c0 * 100 + lane * 4);
            const float4 t1 = *(const float4*)(T + (size_t)c1 * 100 + lane * 4);
            acc.x = fmaf(v0, t0.x, fmaf(v1, t1.x, acc.x));
            acc.y = fmaf(v0, t0.y, fmaf(v1, t1.y, acc.y));
            acc.z = fmaf(v0, t0.z, fmaf(v1, t1.z, acc.z));
            acc.w = fmaf(v0, t0.w, fmaf(v1, t1.w, acc.w));
        }
    }
    if (p < e) {
        int c = g_cols2[p];
        float v = g_vals2[p];
        if (lane < 25) {
            const float4 t4 = *(const float4*)(T + (size_t)c * 100 + lane * 4);
            acc.x = fmaf(v, t4.x, acc.x);
            acc.y = fmaf(v, t4.y, acc.y);
            acc.z = fmaf(v, t4.z, acc.z);
            acc.w = fmaf(v, t4.w, acc.w);
        }
    }
    if (lane < 25) *(float4*)(Out + (size_t)warp * 100 + lane * 4) = acc;
}

// ======================= mma.sync split-bf16 GEMM =======================
// 512 threads: 16 warps = 8 m-tiles x 2 phases; phase 0 -> nc 0..6, phase 1 -> nc 7..12
#define EPI_FINAL   3

#define OFF_AHI 0
#define OFF_ALO 30720
#define OFF_RED 61440
#define SMEM_MMA (61440 + 1024)
#define A_STRIDE 240

__device__ __forceinline__ uint32_t smem_u32(const void* p) {
    uint32_t a;
    asm("{ .reg .u64 t; cvta.to.shared.u64 t, %1; cvt.u32.u64 %0, t; }" : "=r"(a) : "l"(p));
    return a;
}
__device__ __forceinline__ void mma16816(float* c, uint32_t a0, uint32_t a1, uint32_t a2,
                                         uint32_t a3, uint32_t b0, uint32_t b1) {
    asm volatile(
        "mma.sync.aligned.m16n8k16.row.col.f32.bf16.bf16.f32 "
        "{%0,%1,%2,%3}, {%4,%5,%6,%7}, {%8,%9}, {%0,%1,%2,%3};\n"
        : "+f"(c[0]), "+f"(c[1]), "+f"(c[2]), "+f"(c[3])
        : "r"(a0), "r"(a1), "r"(a2), "r"(a3), "r"(b0), "r"(b1));
}
__device__ __forceinline__ void ldsm_x4(uint32_t& r0, uint32_t& r1, uint32_t& r2,
                                        uint32_t& r3, uint32_t addr) {
    asm volatile("ldmatrix.sync.aligned.m8n8.x4.shared.b16 {%0,%1,%2,%3}, [%4];"
        : "=r"(r0), "=r"(r1), "=r"(r2), "=r"(r3) : "r"(addr));
}
__device__ __forceinline__ void ldsm_x4t(uint32_t& r0, uint32_t& r1, uint32_t& r2,
                                         uint32_t& r3, uint32_t addr) {
    asm volatile("ldmatrix.sync.aligned.m8n8.x4.trans.shared.b16 {%0,%1,%2,%3}, [%4];"
        : "=r"(r0), "=r"(r1), "=r"(r2), "=r"(r3) : "r"(addr));
}

template <int NT>
__device__ __forceinline__ void stage_A(char* smem, const float* __restrict__ A,
                                        int row0, int nrows, int tid) {
    bool tail = (row0 + 128 > nrows);
    if (tail) {
        for (int i = tid; i < 61440 / 16; i += NT)
            ((int4*)smem)[i] = make_int4(0, 0, 0, 0);
        __syncthreads();
    } else {
        for (int i = tid; i < 128 * 6; i += NT) {
            int r = i / 6, u = i % 6;
            uint32_t off = (uint32_t)(r * A_STRIDE + 200 + u * 4);
            *(uint32_t*)(smem + OFF_AHI + off) = 0u;
            *(uint32_t*)(smem + OFF_ALO + off) = 0u;
        }
    }
    for (int idx = tid; idx < 128 * 25; idx += NT) {
        int r = idx / 25, q = idx % 25;
        int row = row0 + r;
        if (row < nrows) {
            float4 v = *(const float4*)(A + (size_t)row * 100 + q * 4);
            uint32_t h0, l0, h1, l1;
            split2(v.x, v.y, h0, l0);
            split2(v.z, v.w, h1, l1);
            uint32_t off = (uint32_t)(r * A_STRIDE + q * 8);
            *(uint2*)(smem + OFF_AHI + off) = make_uint2(h0, h1);
            *(uint2*)(smem + OFF_ALO + off) = make_uint2(l0, l1);
        }
    }
}

__device__ __forceinline__ void mainloop7(float acc[7][4], const uint4* __restrict__ Bf,
                                          uint32_t aAddrHi, uint32_t aAddrLo,
                                          int lane, int ncBase, int ncN) {
#pragma unroll
    for (int j = 0; j < 7; j++)
#pragma unroll
        for (int q = 0; q < 4; q++) acc[j][q] = 0.f;
#pragma unroll
    for (int ks = 0; ks < 7; ks++) {
        uint32_t ah0, ah1, ah2, ah3, al0, al1, al2, al3;
        ldsm_x4(ah0, ah1, ah2, ah3, aAddrHi + ks * 32);
        ldsm_x4(al0, al1, al2, al3, aAddrLo + ks * 32);
        const uint4* bp = Bf + ks * 416 + ncBase * 32 + lane;
        uint4 b = bp[0];
#pragma unroll
        for (int j = 0; j < 7; j++) {
            uint4 bn;
            if (j + 1 < ncN) bn = bp[(j + 1) * 32];
            if (j < ncN) {
                mma16816(acc[j], ah0, ah1, ah2, ah3, b.x, b.y);
                mma16816(acc[j], ah0, ah1, ah2, ah3, b.z, b.w);
                mma16816(acc[j], al0, al1, al2, al3, b.x, b.y);
            }
            b = bn;
        }
    }
}

__device__ __forceinline__ void phase_red(float& pA, float& pB, float* Red,
                                          int mt, int phase, int g, int lane, bool isMax) {
    if (isMax) {
        pA = fmaxf(pA, __shfl_xor_sync(0xffffffffu, pA, 1));
        pA = fmaxf(pA, __shfl_xor_sync(0xffffffffu, pA, 2));
        pB = fmaxf(pB, __shfl_xor_sync(0xffffffffu, pB, 1));
        pB = fmaxf(pB, __shfl_xor_sync(0xffffffffu, pB, 2));
    } else {
        pA += __shfl_xor_sync(0xffffffffu, pA, 1);
        pA += __shfl_xor_sync(0xffffffffu, pA, 2);
        pB += __shfl_xor_sync(0xffffffffu, pB, 1);
        pB += __shfl_xor_sync(0xffffffffu, pB, 2);
    }
    __syncthreads();
    if ((lane & 3) == 0) {
        Red[(16 * mt + g) * 2 + phase]     = pA;
        Red[(16 * mt + g + 8) * 2 + phase] = pB;
    }
    __syncthreads();
    int ia = (16 * mt + g) * 2, ib = (16 * mt + g + 8) * 2;
    if (isMax) {
        pA = fmaxf(Red[ia], Red[ia + 1]);
        pB = fmaxf(Red[ib], Red[ib + 1]);
    } else {
        pA = Red[ia] + Red[ia + 1];
        pB = Red[ib] + Red[ib + 1];
    }
}

template <int EPI>
__global__ void __launch_bounds__(512, 2) k_mma(
    const float* __restrict__ A, const uint4* __restrict__ Bf,
    const float* __restrict__ Res, float* __restrict__ C,
    float* __restrict__ Inv1, float* __restrict__ Inv2, int nrows)
{
    extern __shared__ char smem[];
    float* Red = (float*)(smem + OFF_RED);
    int tid = threadIdx.x;
    int w16 = tid >> 5, lane = tid & 31;
    int mt = w16 >> 1, phase = w16 & 1;
    int ncBase = phase ? 7 : 0, ncN = phase ? 6 : 7;
    int g = lane >> 2, i2 = (lane & 3) * 2;
    int row0 = blockIdx.x * 128;

    stage_A<512>(smem, A, row0, nrows, tid);
    __syncthreads();

    uint32_t sb = smem_u32(smem);
    uint32_t aAddrHi = sb + OFF_AHI + (uint32_t)((16 * mt + (lane & 15)) * A_STRIDE) + ((lane >> 4) << 4);
    uint32_t aAddrLo = aAddrHi + (OFF_ALO - OFF_AHI);

    float acc[7][4];
    mainloop7(acc, Bf, aAddrHi, aAddrLo, lane, ncBase, ncN);

    int rA = row0 + 16 * mt + g;
    int rB = rA + 8;

    if (EPI == EPI_FINAL) {
        float sA = 0.f, sB = 0.f;
#pragma unroll
        for (int j = 0; j < 7; j++) {
            if (j < ncN) {
                sA = fmaf(acc[j][0], acc[j][0], fmaf(acc[j][1], acc[j][1], sA));
                sB = fmaf(acc[j][2], acc[j][2], fmaf(acc[j][3], acc[j][3], sB));
            }
        }
        phase_red(sA, sB, Red, mt, phase, g, lane, false);
        float i1A = 1.f / fmaxf(sqrtf(sA), 1e-12f);
        float i1B = 1.f / fmaxf(sqrtf(sB), 1e-12f);
        if (phase == 0 && (lane & 3) == 0) {
            if (rA < nrows) Inv1[rA] = i1A;
            if (rB < nrows) Inv1[rB] = i1B;
        }
        float s2A = 0.f, s2B = 0.f;
#pragma unroll
        for (int j = 0; j < 7; j++) {
            int col = (ncBase + j) * 8 + i2;
            if (j < ncN && col < 100) {
                if (rA < nrows) {
                    float2 r2 = *(const float2*)(Res + (size_t)rA * 100 + col);
                    acc[j][0] += r2.x;
                    acc[j][1] += r2.y;
                }
                if (rB < nrows) {
                    float2 r2 = *(const float2*)(Res + (size_t)rB * 100 + col);
                    acc[j][2] += r2.x;
                    acc[j][3] += r2.y;
                }
                s2A = fmaf(acc[j][0], acc[j][0], fmaf(acc[j][1], acc[j][1], s2A));
                s2B = fmaf(acc[j][2], acc[j][2], fmaf(acc[j][3], acc[j][3], s2B));
            }
        }
        phase_red(s2A, s2B, Red, mt, phase, g, lane, false);
        float i2A = 1.f / fmaxf(sqrtf(s2A), 1e-12f);
        float i2B = 1.f / fmaxf(sqrtf(s2B), 1e-12f);
        if (phase == 0 && (lane & 3) == 0) {
            if (rA < nrows) Inv2[rA] = i2A;
            if (rB < nrows) Inv2[rB] = i2B;
        }
#pragma unroll
        for (int j = 0; j < 7; j++) {
            int col = (ncBase + j) * 8 + i2;
            if (j < ncN && col < 100) {
                if (rA < nrows)
                    *(float2*)(C + (size_t)rA * 100 + col) = make_float2(acc[j][0], acc[j][1]);
                if (rB < nrows)
                    *(float2*)(C + (size_t)rB * 100 + col) = make_float2(acc[j][2], acc[j][3]);
            }
        }
    }
}

// ---- fused3: xs = sp@Wl (store+restage); Ab = relu(xs@W1 + xs); H1 = softmax(Ab@W2) ----
__global__ void __launch_bounds__(512, 2) k_fused(
    const float* __restrict__ SP, const uint4* __restrict__ BfW,
    const uint4* __restrict__ Bf1, const uint4* __restrict__ Bf2,
    float* __restrict__ XSout, float* __restrict__ H1out, int nrows)
{
    extern __shared__ char smem[];
    float* Red = (float*)(smem + OFF_RED);
    int tid = threadIdx.x;
    int w16 = tid >> 5, lane = tid & 31;
    int mt = w16 >> 1, phase = w16 & 1;
    int ncBase = phase ? 7 : 0, ncN = phase ? 6 : 7;
    int g = lane >> 2, i2 = (lane & 3) * 2;
    int row0 = blockIdx.x * 128;

    stage_A<512>(smem, SP, row0, nrows, tid);
    __syncthreads();

    uint32_t sb = smem_u32(smem);
    uint32_t aAddrHi = sb + OFF_AHI + (uint32_t)((16 * mt + (lane & 15)) * A_STRIDE) + ((lane >> 4) << 4);
    uint32_t aAddrLo = aAddrHi + (OFF_ALO - OFF_AHI);

    int rLocA = 16 * mt + g, rLocB = rLocA + 8;
    int rA = row0 + rLocA, rB = row0 + rLocB;

    float acc[7][4];

    // ---- stage 1: xs = sp @ W_item[l] ----
    mainloop7(acc, BfW, aAddrHi, aAddrLo, lane, ncBase, ncN);
    __syncthreads();   // sp reads done before overwrite
#pragma unroll
    for (int j = 0; j < 7; j++) {
        int col = (ncBase + j) * 8 + i2;
        if (j < ncN) {
            if (col < 100) {
                if (rA < nrows)
                    *(float2*)(XSout + (size_t)rA * 100 + col) = make_float2(acc[j][0], acc[j][1]);
                if (rB < nrows)
                    *(float2*)(XSout + (size_t)rB * 100 + col) = make_float2(acc[j][2], acc[j][3]);
            }
            uint32_t h, l;
            split2(acc[j][0], acc[j][1], h, l);   // pads: acc = 0 (BfW zero-padded)
            *(uint32_t*)(smem + OFF_AHI + rLocA * A_STRIDE + col * 2) = h;
            *(uint32_t*)(smem + OFF_ALO + rLocA * A_STRIDE + col * 2) = l;
            split2(acc[j][2], acc[j][3], h, l);
            *(uint32_t*)(smem + OFF_AHI + rLocB * A_STRIDE + col * 2) = h;
            *(uint32_t*)(smem + OFF_ALO + rLocB * A_STRIDE + col * 2) = l;
        }
    }
    __syncthreads();

    // ---- stage 2: Ab = relu(xs@W1 + xs), xs residual from smem ----
    mainloop7(acc, Bf1, aAddrHi, aAddrLo, lane, ncBase, ncN);
    __syncthreads();
#pragma unroll
    for (int j = 0; j < 7; j++) {
        int col = (ncBase + j) * 8 + i2;
        if (j < ncN) {
            uint32_t* pHA = (uint32_t*)(smem + OFF_AHI + rLocA * A_STRIDE + col * 2);
            uint32_t* pLA = (uint32_t*)(smem + OFF_ALO + rLocA * A_STRIDE + col * 2);
            uint32_t* pHB = (uint32_t*)(smem + OFF_AHI + rLocB * A_STRIDE + col * 2);
            uint32_t* pLB = (uint32_t*)(smem + OFF_ALO + rLocB * A_STRIDE + col * 2);
            uint32_t hA = *pHA, lA = *pLA, hB = *pHB, lB = *pLB;
            float vA0 = fmaxf(acc[j][0] + recon2(hA, lA, 0), 0.f);
            float vA1 = fmaxf(acc[j][1] + recon2(hA, lA, 1), 0.f);
            float vB0 = fmaxf(acc[j][2] + recon2(hB, lB, 0), 0.f);
            float vB1 = fmaxf(acc[j][3] + recon2(hB, lB, 1), 0.f);
            uint32_t h, l;
            split2(vA0, vA1, h, l);
            *pHA = h; *pLA = l;
            split2(vB0, vB1, h, l);
            *pHB = h; *pLB = l;
        }
    }
    __syncthreads();

    // ---- stage 3: H1 = softmax(Ab@W2) ----
    mainloop7(acc, Bf2, aAddrHi, aAddrLo, lane, ncBase, ncN);

    float mA = -1e30f, mB = -1e30f;
#pragma unroll
    for (int j = 0; j < 7; j++) {
        int col = (ncBase + j) * 8 + i2;
        if (j < ncN && col < 100) {
            mA = fmaxf(mA, fmaxf(acc[j][0], acc[j][1]));
            mB = fmaxf(mB, fmaxf(acc[j][2], acc[j][3]));
        }
    }
    phase_red(mA, mB, Red, mt, phase, g, lane, true);
    float sA = 0.f, sB = 0.f;
#pragma unroll
    for (int j = 0; j < 7; j++) {
        int col = (ncBase + j) * 8 + i2;
        if (j < ncN && col < 100) {
            acc[j][0] = __expf(acc[j][0] - mA);
            acc[j][1] = __expf(acc[j][1] - mA);
            acc[j][2] = __expf(acc[j][2] - mB);
            acc[j][3] = __expf(acc[j][3] - mB);
            sA += acc[j][0] + acc[j][1];
            sB += acc[j][2] + acc[j][3];
        }
    }
    phase_red(sA, sB, Red, mt, phase, g, lane, false);
    float iA = 1.f / sA, iB = 1.f / sB;
#pragma unroll
    for (int j = 0; j < 7; j++) {
        int col = (ncBase + j) * 8 + i2;
        if (j < ncN && col < 100) {
            if (rA < nrows)
                *(float2*)(H1out + (size_t)rA * 100 + col) =
                    make_float2(acc[j][0] * iA, acc[j][1] * iA);
            if (rB < nrows)
                *(float2*)(H1out + (size_t)rB * 100 + col) =
                    make_float2(acc[j][2] * iB, acc[j][3] * iB);
        }
    }
}

// ======================= h = H1^T @ X via mma (+ last-block preps h frags) =======================
#define OC_XHI 0
#define OC_XLO 15360
#define OC_HHI 30720
#define OC_HLO 46080
#define SMEM_OUT 61440
#define OUTER_GRID 444

__global__ void __launch_bounds__(224) k_outer_mma(const float* __restrict__ H1,
                                                   const float* __restrict__ X,
                                                   float* __restrict__ hout) {
    extern __shared__ char smem[];
    int tid = threadIdx.x;
    int w = tid >> 5, lane = tid & 31;
    int g = lane >> 2, i2 = (lane & 3) * 2;

    for (int i = tid; i < 64 * 6 * 4; i += 224) {
        int t = i / (64 * 6), r = (i / 6) % 64, u = i % 6;
        *(uint32_t*)(smem + t * 15360 + r * 240 + 200 + u * 4) = 0u;
    }

    float acc[13][4];
#pragma unroll
    for (int nc = 0; nc < 13; nc++)
#pragma unroll
        for (int q = 0; q < 4; q++) acc[nc][q] = 0.f;

    uint32_t sb = smem_u32(smem);
    uint32_t aRow = (uint32_t)((lane & 7) + ((lane >> 4) << 3));
    uint32_t aAddrHi = sb + OC_HHI + aRow * 240 + (uint32_t)(((lane >> 3) & 1) << 4) + (uint32_t)(w * 32);
    uint32_t aAddrLo = aAddrHi + (OC_HLO - OC_HHI);
    uint32_t bRow = (uint32_t)((lane & 7) + (((lane >> 3) & 1) << 3));
    uint32_t bAddrHi = sb + OC_XHI + bRow * 240 + (uint32_t)((lane >> 4) << 4);
    uint32_t bAddrLo = bAddrHi + (OC_XLO - OC_XHI);

    const int nch = (NN + 63) / 64;
    for (int ch = blockIdx.x; ch < nch; ch += OUTER_GRID) {
        int base = ch * 64;
        bool tail = (base + 64 > NN);
        __syncthreads();
        if (tail) {
            for (int i = tid; i < SMEM_OUT / 16; i += 224)
                ((int4*)smem)[i] = make_int4(0, 0, 0, 0);
            __syncthreads();
        }
        for (int idx = tid; idx < 64 * 25; idx += 224) {
            int r = idx / 25, q = idx % 25;
            int node = base + r;
            if (node < NN) {
                uint32_t off = (uint32_t)(r * 240 + q * 8);
                float4 v = *(const float4*)(X + (size_t)node * 100 + q * 4);
                uint32_t h0, l0, h1, l1;
                split2(v.x, v.y, h0, l0);
                split2(v.z, v.w, h1, l1);
                *(uint2*)(smem + OC_XHI + off) = make_uint2(h0, h1);
                *(uint2*)(smem + OC_XLO + off) = make_uint2(l0, l1);
                float4 u = *(const float4*)(H1 + (size_t)node * 100 + q * 4);
                split2(u.x, u.y, h0, l0);
                split2(u.z, u.w, h1, l1);
                *(uint2*)(smem + OC_HHI + off) = make_uint2(h0, h1);
                *(uint2*)(smem + OC_HLO + off) = make_uint2(l0, l1);
            }
        }
        __syncthreads();

#pragma unroll
        for (int ks = 0; ks < 4; ks++) {
            uint32_t ah0, ah1, ah2, ah3, al0, al1, al2, al3;
            ldsm_x4t(ah0, ah1, ah2, ah3, aAddrHi + (uint32_t)(ks * 16 * 240));
            ldsm_x4t(al0, al1, al2, al3, aAddrLo + (uint32_t)(ks * 16 * 240));
#pragma unroll
            for (int c3 = 0; c3 < 7; c3++) {
                uint32_t bh0, bh1, bh2, bh3, bl0, bl1, bl2, bl3;
                ldsm_x4t(bh0, bh1, bh2, bh3, bAddrHi + (uint32_t)(ks * 16 * 240 + c3 * 32));
                ldsm_x4t(bl0, bl1, bl2, bl3, bAddrLo + (uint32_t)(ks * 16 * 240 + c3 * 32));
                int nc = 2 * c3;
                mma16816(acc[nc], ah0, ah1, ah2, ah3, bh0, bh1);
                mma16816(acc[nc], ah0, ah1, ah2, ah3, bl0, bl1);
                mma16816(acc[nc], al0, al1, al2, al3, bh0, bh1);
                if (c3 < 6) {
                    mma16816(acc[nc + 1], ah0, ah1, ah2, ah3, bh2, bh3);
                    mma16816(acc[nc + 1], ah0, ah1, ah2, ah3, bl2, bl3);
                    mma16816(acc[nc + 1], al0, al1, al2, al3, bh2, bh3);
                }
            }
        }
    }

    int kkA = 16 * w + g;
    int kkB = kkA + 8;
#pragma unroll
    for (int nc = 0; nc < 13; nc++) {
        int col = nc * 8 + i2;
        if (col < 100) {
            if (kkA < 100) {
                atomicAdd(&hout[kkA * 100 + col],     acc[nc][0]);
                atomicAdd(&hout[kkA * 100 + col + 1], acc[nc][1]);
            }
            if (kkB < 100) {
                atomicAdd(&hout[kkB * 100 + col],     acc[nc][2]);
                atomicAdd(&hout[kkB * 100 + col + 1], acc[nc][3]);
            }
        }
    }

    // last block preps h fragments (replaces k_preph launch)
    __threadfence();
    __syncthreads();
    __shared__ int isLast;
    if (tid == 0) {
        int c = atomicAdd(&g_outer_done, 1);
        isLast = (c == OUTER_GRID - 1) ? 1 : 0;
    }
    __syncthreads();
    if (isLast) {
        if (tid == 0) g_outer_done = 0;
        prep_frag(hout, 5, tid, 224);
    }
}

// ---------------- final output (defers fin/finh reconstruction) ----------------
__global__ void k_final(float* __restrict__ out, const float* __restrict__ emb, int out_n) {
    int i4 = blockIdx.x * blockDim.x + threadIdx.x;
    const int half4 = ND / 4;
    if (i4 < half4) {
        int row = (i4 * 4) / 100;
        float4 a = ((const float4*)emb)[i4];
#pragma unroll
        for (int l = 0; l < LL; l++) {
            float4 xv = ((const float4*)g_xl[l])[i4];
            float iv = g_inv2[l][row];
            a.x = fmaf(xv.x, iv, a.x);
            a.y = fmaf(xv.y, iv, a.y);
            a.z = fmaf(xv.z, iv, a.z);
            a.w = fmaf(xv.w, iv, a.w);
        }
        a.x *= 0.25f; a.y *= 0.25f; a.z *= 0.25f; a.w *= 0.25f;
        ((float4*)out)[i4] = a;
    } else if (i4 < 2 * half4) {
        int j4 = i4 - half4;
        int row = (j4 * 4) / 100;
        float4 a = make_float4(0.f, 0.f, 0.f, 0.f);
#pragma unroll
        for (int l = 0; l < LL; l++) {
            float4 xv = ((const float4*)g_xl[l])[j4];
            float4 sv = ((const float4*)g_xsl[l])[j4];
            float iv = g_inv1[l][row];
            a.x = fmaf(xv.x - sv.x, iv, a.x);
            a.y = fmaf(xv.y - sv.y, iv, a.y);
            a.z = fmaf(xv.z - sv.z, iv, a.z);
            a.w = fmaf(xv.w - sv.w, iv, a.w);
        }
        const float third = 1.0f / 3.0f;
        a.x *= third; a.y *= third; a.z *= third; a.w *= third;
        ((float4*)out)[i4] = a;
    }
}

// ---------------- launcher ----------------
extern "C" void kernel_launch(void* const* d_in, const int* in_sizes, int n_in,
                              void* d_out, int out_size) {
    const float* embedding = (const float*)d_in[0];
    // d_in[1] = adj : mathematically cancels (softmax row-sums = 1)
    const float* edge_vals = (const float*)d_in[2];
    const float* W_item    = (const float*)d_in[3];
    const float* W_i1      = (const float*)d_in[4];
    const float* W_i2      = (const float*)d_in[5];
    const int*   edge_rows = (const int*)d_in[6];
    const int*   edge_cols = (const int*)d_in[7];
    float* out = (float*)d_out;

    float *sp, *xl, *xsl, *H1, *hh, *inv1, *inv2;
    cudaGetSymbolAddress((void**)&sp,   g_sp);
    cudaGetSymbolAddress((void**)&xl,   g_xl);
    cudaGetSymbolAddress((void**)&xsl,  g_xsl);
    cudaGetSymbolAddress((void**)&H1,   g_H1);
    cudaGetSymbolAddress((void**)&hh,   g_hh);
    cudaGetSymbolAddress((void**)&inv1, g_inv1);
    cudaGetSymbolAddress((void**)&inv2, g_inv2);
    int *cnt;
    cudaGetSymbolAddress((void**)&cnt, g_cnt);
    uint4 *bf;
    cudaGetSymbolAddress((void**)&bf, g_Bf);

    cudaFuncSetAttribute(k_mma<EPI_FINAL>, cudaFuncAttributeMaxDynamicSharedMemorySize, SMEM_MMA);
    cudaFuncSetAttribute(k_fused,          cudaFuncAttributeMaxDynamicSharedMemorySize, SMEM_MMA);
    cudaFuncSetAttribute(k_outer_mma,      cudaFuncAttributeMaxDynamicSharedMemorySize, SMEM_OUT);

    // side stream + fork/join events (created once; host-side resources only)
    static cudaStream_t s2 = nullptr;
    static cudaEvent_t evFork = nullptr, evJoin = nullptr;
    if (s2 == nullptr) {
        cudaStreamCreateWithFlags(&s2, cudaStreamNonBlocking);
        cudaEventCreateWithFlags(&evFork, cudaEventDisableTiming);
        cudaEventCreateWithFlags(&evJoin, cudaEventDisableTiming);
    }

    const int GB = (NN + 127) / 128;   // 782
    auto BF = [&](int s) { return bf + (size_t)s * 2912; };

    // fork: CSR build + zeroing on s2, weight prep on main
    cudaEventRecord(evFork, 0);
    cudaStreamWaitEvent(s2, evFork, 0);

    k_prep5<<<5, 256>>>(W_item, W_i1, W_i2);                   // main
    k_zeroi<<<(NN + 255) / 256, 256, 0, s2>>>(cnt, NN);        // s2
    k_zerof<<<(LL * KD + 255) / 256, 256, 0, s2>>>(hh, LL * KD); // s2
    k_hist<<<1024, 256, 0, s2>>>(edge_rows);                   // s2
    k_scan1<<<NB_SCAN, 1024, 0, s2>>>();                       // s2
    k_scan2<<<1, 1, 0, s2>>>();                                // s2
    k_scan3<<<(NN + 255) / 256, 256, 0, s2>>>();               // s2
    k_scatter<<<1024, 256, 0, s2>>>(edge_rows, edge_cols, edge_vals); // s2
    cudaEventRecord(evJoin, s2);
    cudaStreamWaitEvent(0, evJoin, 0);

    const float* xin = embedding;
    for (int layer = 0; layer < LL; layer++) {
        float* xs_l = xsl + (size_t)layer * ND;
        float* x_l  = xl  + (size_t)layer * ND;
        float* h_l  = hh  + (size_t)layer * KD;
        // sp = A_sparse @ x   (commuted: W applied after)
        k_spmm<<<(NN * 32 + 255) / 256, 256>>>(xin, sp);
        // xs = sp @ W_item[l]; Ab = relu(xs@W1+xs); H1 = softmax(Ab@W2)
        k_fused<<<GB, 512, SMEM_MMA>>>(sp, BF(layer), BF(3), BF(4), xs_l, H1, NN);
        // h = H1^T @ xs  (+ last block preps h fragments)
        k_outer_mma<<<OUTER_GRID, 224, SMEM_OUT>>>(H1, xs_l, h_l);
        // x = H1@h + xs ; store inv1/inv2
        k_mma<EPI_FINAL><<<GB, 512, SMEM_MMA>>>(H1, BF(5), xs_l, x_l,
                                                inv1 + (size_t)layer * NN,
                                                inv2 + (size_t)layer * NN, NN);
        xin = x_l;
    }

    k_final<<<(ND / 2 + 255) / 256, 256>>>(out, embedding, out_size);
}

// round 17
// speedup vs baseline: 1.0487x; 1.0487x over previous
#include <cuda_runtime.h>
#include <cuda_bf16.h>
#include <cuda_fp16.h>
#include <cstdint>

#define NN   100000
#define DD   100
#define KK   100
#define LL   3
#define NNZS 1600000

#define ND (NN*DD)
#define KD (KK*DD)

// fp16 t scaling: store t*2^-10, unscale in spmm (exact power-of-two, no precision loss)
#define T_SCALE_DN 0.0009765625f
#define T_SCALE_UP 1024.0f

// ---------------- device scratch ----------------
__device__ __half g_th [ND];      // t = (x @ W_item) * 2^-10, fp16 (only consumed by spmm)
__device__ float g_xl [LL][ND];
__device__ float g_xsl[LL][ND];
__device__ float g_H1 [NN*KK];
__device__ float g_hh [LL][KD];
__device__ float g_inv1[LL][NN];
__device__ float g_inv2[LL][NN];
__device__ int   g_cnt   [NN];
__device__ int   g_rowptr[NN+1];
__device__ int   g_cursor[NN];
__device__ int   g_cols2 [NNZS];
__device__ float g_vals2 [NNZS];
__device__ int   g_bsums [128];
// B in mma fragment order: idx = (ks*13+nc)*32+lane -> uint4{bh0,bh1,bl0,bl1}
// slots: 0..2 = W_item[l], 3 = W_i1, 4 = W_i2, 5 = h (per layer)
__device__ uint4 g_Bf[6][2912];

// ---------------- small utility kernels ----------------
__global__ void k_zerof(float* __restrict__ p, int n) {
    int i = blockIdx.x * blockDim.x + threadIdx.x;
    if (i < n) p[i] = 0.f;
}
__global__ void k_zeroi(int* __restrict__ p, int n) {
    int i = blockIdx.x * blockDim.x + threadIdx.x;
    if (i < n) p[i] = 0;
}

__device__ __forceinline__ void split2(float a, float b, uint32_t& hi, uint32_t& lo) {
    __nv_bfloat16 ah = __float2bfloat16(a), bh = __float2bfloat16(b);
    float ar = a - __bfloat162float(ah);
    float br = b - __bfloat162float(bh);
    __nv_bfloat16 al = __float2bfloat16(ar), bl = __float2bfloat16(br);
    hi = (uint32_t)__bfloat16_as_ushort(ah) | ((uint32_t)__bfloat16_as_ushort(bh) << 16);
    lo = (uint32_t)__bfloat16_as_ushort(al) | ((uint32_t)__bfloat16_as_ushort(bl) << 16);
}
__device__ __forceinline__ float recon2(uint32_t h, uint32_t l, int which) {
    uint16_t hb = which ? (uint16_t)(h >> 16) : (uint16_t)(h & 0xffff);
    uint16_t lb = which ? (uint16_t)(l >> 16) : (uint16_t)(l & 0xffff);
    return __bfloat162float(__ushort_as_bfloat16(hb)) + __bfloat162float(__ushort_as_bfloat16(lb));
}

// ---------------- weight prep into fragment order ----------------
__device__ __forceinline__ void prep_frag(const float* __restrict__ S, int slot, int tid, int nthr) {
    for (int idx = tid; idx < 2912; idx += nthr) {
        int ks = idx / 416;
        int rem = idx - ks * 416;
        int nc = rem >> 5, lane = rem & 31;
        int g = lane >> 2, tp = lane & 3;
        int n = nc * 8 + g;
        int ka = ks * 16 + tp * 2;
        int kb = ka + 8;
        float wa0 = (n < 100 && ka     < 100) ? S[ka * 100 + n]       : 0.f;
        float wa1 = (n < 100 && ka + 1 < 100) ? S[(ka + 1) * 100 + n] : 0.f;
        float wb0 = (n < 100 && kb     < 100) ? S[kb * 100 + n]       : 0.f;
        float wb1 = (n < 100 && kb + 1 < 100) ? S[(kb + 1) * 100 + n] : 0.f;
        uint32_t h0, l0, h1, l1;
        split2(wa0, wa1, h0, l0);
        split2(wb0, wb1, h1, l1);
        g_Bf[slot][idx] = make_uint4(h0, h1, l0, l1);
    }
}
__global__ void k_prep5(const float* __restrict__ W_item, const float* __restrict__ W_i1,
                        const float* __restrict__ W_i2) {
    int b = blockIdx.x;
    const float* S = (b < 3) ? (W_item + b * 10000) : ((b == 3) ? W_i1 : W_i2);
    prep_frag(S, b, threadIdx.x, blockDim.x);
}
__global__ void k_preph(const float* __restrict__ h) {
    prep_frag(h, 5, blockIdx.x * blockDim.x + threadIdx.x, gridDim.x * blockDim.x);
}

// ---------------- CSR build ----------------
__global__ void k_hist(const int* __restrict__ rows) {
    for (int e = blockIdx.x * blockDim.x + threadIdx.x; e < NNZS; e += gridDim.x * blockDim.x)
        atomicAdd(&g_cnt[rows[e]], 1);
}

#define NB_SCAN ((NN + 1023) / 1024)

__global__ void k_scan1() {
    __shared__ int s[1024];
    int tid = threadIdx.x;
    int i = blockIdx.x * 1024 + tid;
    int v = (i < NN) ? g_cnt[i] : 0;
    s[tid] = v;
    __syncthreads();
    for (int off = 1; off < 1024; off <<= 1) {
        int t = 0;
        if (tid >= off) t = s[tid - off];
        __syncthreads();
        if (tid >= off) s[tid] += t;
        __syncthreads();
    }
    if (i < NN) g_rowptr[i] = s[tid] - v;
    if (tid == 0) g_bsums[blockIdx.x] = s[1023];
}
__global__ void k_scan2() {
    int run = 0;
    for (int b = 0; b < NB_SCAN; b++) { int v = g_bsums[b]; g_bsums[b] = run; run += v; }
}
__global__ void k_scan3() {
    int i = blockIdx.x * blockDim.x + threadIdx.x;
    if (i < NN) {
        int v = g_rowptr[i] + g_bsums[i >> 10];
        g_rowptr[i] = v;
        g_cursor[i] = v;
    }
    if (i == 0) g_rowptr[NN] = NNZS;
}
__global__ void k_scatter(const int* __restrict__ rows, const int* __restrict__ cols,
                          const float* __restrict__ vals) {
    for (int e = blockIdx.x * blockDim.x + threadIdx.x; e < NNZS; e += gridDim.x * blockDim.x) {
        int r = rows[e];
        int p = atomicAdd(&g_cursor[r], 1);
        g_cols2[p] = cols[e];
        g_vals2[p] = vals[e];
    }
}

// ---------------- SpMM (warp per row, fp16 gather, fp32 accum, unscale on output) ----------------
__global__ void k_spmm(const __half* __restrict__ T, float* __restrict__ Out) {
    int warp = (blockIdx.x * blockDim.x + threadIdx.x) >> 5;
    int lane = threadIdx.x & 31;
    if (warp >= NN) return;
    int s = g_rowptr[warp], e = g_rowptr[warp + 1];
    float4 acc = make_float4(0.f, 0.f, 0.f, 0.f);
    int p = s;
    for (; p + 1 < e; p += 2) {
        int c0 = g_cols2[p], c1 = g_cols2[p + 1];
        float v0 = g_vals2[p], v1 = g_vals2[p + 1];
        if (lane < 25) {
            const __half2* r0 = (const __half2*)(T + (size_t)c0 * 100) + lane * 2;
            const __half2* r1 = (const __half2*)(T + (size_t)c1 * 100) + lane * 2;
            float2 a0 = __half22float2(r0[0]), a1 = __half22float2(r0[1]);
            float2 b0 = __half22float2(r1[0]), b1 = __half22float2(r1[1]);
            acc.x = fmaf(v0, a0.x, fmaf(v1, b0.x, acc.x));
            acc.y = fmaf(v0, a0.y, fmaf(v1, b0.y, acc.y));
            acc.z = fmaf(v0, a1.x, fmaf(v1, b1.x, acc.z));
            acc.w = fmaf(v0, a1.y, fmaf(v1, b1.y, acc.w));
        }
    }
    if (p < e) {
        int c = g_cols2[p];
        float v = g_vals2[p];
        if (lane < 25) {
            const __half2* r0 = (const __half2*)(T + (size_t)c * 100) + lane * 2;
            float2 a0 = __half22float2(r0[0]), a1 = __half22float2(r0[1]);
            acc.x = fmaf(v, a0.x, acc.x);
            acc.y = fmaf(v, a0.y, acc.y);
            acc.z = fmaf(v, a1.x, acc.z);
            acc.w = fmaf(v, a1.y, acc.w);
        }
    }
    if (lane < 25) {
        acc.x *= T_SCALE_UP; acc.y *= T_SCALE_UP;
        acc.z *= T_SCALE_UP; acc.w *= T_SCALE_UP;
        *(float4*)(Out + (size_t)warp * 100 + lane * 4) = acc;
    }
}

// ======================= mma.sync split-bf16 GEMM =======================
// 512 threads: 16 warps = 8 m-tiles x 2 phases; phase 0 -> nc 0..6, phase 1 -> nc 7..12
#define EPI_NONE    0
#define EPI_FINAL   3

#define OFF_AHI 0
#define OFF_ALO 30720
#define OFF_RED 61440
#define SMEM_MMA (61440 + 1024)
#define A_STRIDE 240

__device__ __forceinline__ uint32_t smem_u32(const void* p) {
    uint32_t a;
    asm("{ .reg .u64 t; cvta.to.shared.u64 t, %1; cvt.u32.u64 %0, t; }" : "=r"(a) : "l"(p));
    return a;
}
__device__ __forceinline__ void mma16816(float* c, uint32_t a0, uint32_t a1, uint32_t a2,
                                         uint32_t a3, uint32_t b0, uint32_t b1) {
    asm volatile(
        "mma.sync.aligned.m16n8k16.row.col.f32.bf16.bf16.f32 "
        "{%0,%1,%2,%3}, {%4,%5,%6,%7}, {%8,%9}, {%0,%1,%2,%3};\n"
        : "+f"(c[0]), "+f"(c[1]), "+f"(c[2]), "+f"(c[3])
        : "r"(a0), "r"(a1), "r"(a2), "r"(a3), "r"(b0), "r"(b1));
}
__device__ __forceinline__ void ldsm_x4(uint32_t& r0, uint32_t& r1, uint32_t& r2,
                                        uint32_t& r3, uint32_t addr) {
    asm volatile("ldmatrix.sync.aligned.m8n8.x4.shared.b16 {%0,%1,%2,%3}, [%4];"
        : "=r"(r0), "=r"(r1), "=r"(r2), "=r"(r3) : "r"(addr));
}
__device__ __forceinline__ void ldsm_x4t(uint32_t& r0, uint32_t& r1, uint32_t& r2,
                                         uint32_t& r3, uint32_t addr) {
    asm volatile("ldmatrix.sync.aligned.m8n8.x4.trans.shared.b16 {%0,%1,%2,%3}, [%4];"
        : "=r"(r0), "=r"(r1), "=r"(r2), "=r"(r3) : "r"(addr));
}

template <int NT>
__device__ __forceinline__ void stage_A(char* smem, const float* __restrict__ A,
                                        int row0, int nrows, int tid) {
    bool tail = (row0 + 128 > nrows);
    if (tail) {
        for (int i = tid; i < 61440 / 16; i += NT)
            ((int4*)smem)[i] = make_int4(0, 0, 0, 0);
        __syncthreads();
    } else {
        for (int i = tid; i < 128 * 6; i += NT) {
            int r = i / 6, u = i % 6;
            uint32_t off = (uint32_t)(r * A_STRIDE + 200 + u * 4);
            *(uint32_t*)(smem + OFF_AHI + off) = 0u;
            *(uint32_t*)(smem + OFF_ALO + off) = 0u;
        }
    }
    for (int idx = tid; idx < 128 * 25; idx += NT) {
        int r = idx / 25, q = idx % 25;
        int row = row0 + r;
        if (row < nrows) {
            float4 v = *(const float4*)(A + (size_t)row * 100 + q * 4);
            uint32_t h0, l0, h1, l1;
            split2(v.x, v.y, h0, l0);
            split2(v.z, v.w, h1, l1);
            uint32_t off = (uint32_t)(r * A_STRIDE + q * 8);
            *(uint2*)(smem + OFF_AHI + off) = make_uint2(h0, h1);
            *(uint2*)(smem + OFF_ALO + off) = make_uint2(l0, l1);
        }
    }
}

__device__ __forceinline__ void mainloop7(float acc[7][4], const uint4* __restrict__ Bf,
                                          uint32_t aAddrHi, uint32_t aAddrLo,
                                          int lane, int ncBase, int ncN) {
#pragma unroll
    for (int j = 0; j < 7; j++)
#pragma unroll
        for (int q = 0; q < 4; q++) acc[j][q] = 0.f;
#pragma unroll
    for (int ks = 0; ks < 7; ks++) {
        uint32_t ah0, ah1, ah2, ah3, al0, al1, al2, al3;
        ldsm_x4(ah0, ah1, ah2, ah3, aAddrHi + ks * 32);
        ldsm_x4(al0, al1, al2, al3, aAddrLo + ks * 32);
        const uint4* bp = Bf + ks * 416 + ncBase * 32 + lane;
        uint4 b = bp[0];
#pragma unroll
        for (int j = 0; j < 7; j++) {
            uint4 bn;
            if (j + 1 < ncN) bn = bp[(j + 1) * 32];
            if (j < ncN) {
                mma16816(acc[j], ah0, ah1, ah2, ah3, b.x, b.y);
                mma16816(acc[j], ah0, ah1, ah2, ah3, b.z, b.w);
                mma16816(acc[j], al0, al1, al2, al3, b.x, b.y);
            }
            b = bn;
        }
    }
}

__device__ __forceinline__ void phase_red(float& pA, float& pB, float* Red,
                                          int mt, int phase, int g, int lane, bool isMax) {
    if (isMax) {
        pA = fmaxf(pA, __shfl_xor_sync(0xffffffffu, pA, 1));
        pA = fmaxf(pA, __shfl_xor_sync(0xffffffffu, pA, 2));
        pB = fmaxf(pB, __shfl_xor_sync(0xffffffffu, pB, 1));
        pB = fmaxf(pB, __shfl_xor_sync(0xffffffffu, pB, 2));
    } else {
        pA += __shfl_xor_sync(0xffffffffu, pA, 1);
        pA += __shfl_xor_sync(0xffffffffu, pA, 2);
        pB += __shfl_xor_sync(0xffffffffu, pB, 1);
        pB += __shfl_xor_sync(0xffffffffu, pB, 2);
    }
    __syncthreads();
    if ((lane & 3) == 0) {
        Red[(16 * mt + g) * 2 + phase]     = pA;
        Red[(16 * mt + g + 8) * 2 + phase] = pB;
    }
    __syncthreads();
    int ia = (16 * mt + g) * 2, ib = (16 * mt + g + 8) * 2;
    if (isMax) {
        pA = fmaxf(Red[ia], Red[ia + 1]);
        pB = fmaxf(Red[ib], Red[ib + 1]);
    } else {
        pA = Red[ia] + Red[ia + 1];
        pB = Red[ib] + Red[ib + 1];
    }
}

// EPI_NONE: Ch(half) = (A@B) * 2^-10 ; EPI_FINAL: hraw=A@B; Inv1; x=hraw+Res; Inv2; C=x
template <int EPI>
__global__ void __launch_bounds__(512, 2) k_mma(
    const float* __restrict__ A, const uint4* __restrict__ Bf,
    const float* __restrict__ Res, float* __restrict__ C, __half* __restrict__ Ch,
    float* __restrict__ Inv1, float* __restrict__ Inv2, int nrows)
{
    extern __shared__ char smem[];
    float* Red = (float*)(smem + OFF_RED);
    int tid = threadIdx.x;
    int w16 = tid >> 5, lane = tid & 31;
    int mt = w16 >> 1, phase = w16 & 1;
    int ncBase = phase ? 7 : 0, ncN = phase ? 6 : 7;
    int g = lane >> 2, i2 = (lane & 3) * 2;
    int row0 = blockIdx.x * 128;

    stage_A<512>(smem, A, row0, nrows, tid);
    __syncthreads();

    uint32_t sb = smem_u32(smem);
    uint32_t aAddrHi = sb + OFF_AHI + (uint32_t)((16 * mt + (lane & 15)) * A_STRIDE) + ((lane >> 4) << 4);
    uint32_t aAddrLo = aAddrHi + (OFF_ALO - OFF_AHI);

    float acc[7][4];
    mainloop7(acc, Bf, aAddrHi, aAddrLo, lane, ncBase, ncN);

    int rA = row0 + 16 * mt + g;
    int rB = rA + 8;

    if (EPI == EPI_NONE) {
#pragma unroll
        for (int j = 0; j < 7; j++) {
            int col = (ncBase + j) * 8 + i2;
            if (j < ncN && col < 100) {
                if (rA < nrows)
                    *(__half2*)(Ch + (size_t)rA * 100 + col) =
                        __floats2half2_rn(acc[j][0] * T_SCALE_DN, acc[j][1] * T_SCALE_DN);
                if (rB < nrows)
                    *(__half2*)(Ch + (size_t)rB * 100 + col) =
                        __floats2half2_rn(acc[j][2] * T_SCALE_DN, acc[j][3] * T_SCALE_DN);
            }
        }
    }
    if (EPI == EPI_FINAL) {
        float sA = 0.f, sB = 0.f;
#pragma unroll
        for (int j = 0; j < 7; j++) {
            if (j < ncN) {
                sA = fmaf(acc[j][0], acc[j][0], fmaf(acc[j][1], acc[j][1], sA));
                sB = fmaf(acc[j][2], acc[j][2], fmaf(acc[j][3], acc[j][3], sB));
            }
        }
        phase_red(sA, sB, Red, mt, phase, g, lane, false);
        float i1A = 1.f / fmaxf(sqrtf(sA), 1e-12f);
        float i1B = 1.f / fmaxf(sqrtf(sB), 1e-12f);
        if (phase == 0 && (lane & 3) == 0) {
            if (rA < nrows) Inv1[rA] = i1A;
            if (rB < nrows) Inv1[rB] = i1B;
        }
        float s2A = 0.f, s2B = 0.f;
#pragma unroll
        for (int j = 0; j < 7; j++) {
            int col = (ncBase + j) * 8 + i2;
            if (j < ncN && col < 100) {
                if (rA < nrows) {
                    float2 r2 = *(const float2*)(Res + (size_t)rA * 100 + col);
                    acc[j][0] += r2.x;
                    acc[j][1] += r2.y;
                }
                if (rB < nrows) {
                    float2 r2 = *(const float2*)(Res + (size_t)rB * 100 + col);
                    acc[j][2] += r2.x;
                    acc[j][3] += r2.y;
                }
                s2A = fmaf(acc[j][0], acc[j][0], fmaf(acc[j][1], acc[j][1], s2A));
                s2B = fmaf(acc[j][2], acc[j][2], fmaf(acc[j][3], acc[j][3], s2B));
            }
        }
        phase_red(s2A, s2B, Red, mt, phase, g, lane, false);
        float i2A = 1.f / fmaxf(sqrtf(s2A), 1e-12f);
        float i2B = 1.f / fmaxf(sqrtf(s2B), 1e-12f);
        if (phase == 0 && (lane & 3) == 0) {
            if (rA < nrows) Inv2[rA] = i2A;
            if (rB < nrows) Inv2[rB] = i2B;
        }
#pragma unroll
        for (int j = 0; j < 7; j++) {
            int col = (ncBase + j) * 8 + i2;
            if (j < ncN && col < 100) {
                if (rA < nrows)
                    *(float2*)(C + (size_t)rA * 100 + col) = make_float2(acc[j][0], acc[j][1]);
                if (rB < nrows)
                    *(float2*)(C + (size_t)rB * 100 + col) = make_float2(acc[j][2], acc[j][3]);
            }
        }
    }
}

// ---- fused: Ab = relu(xs@W1 + xs) (smem-resident), H1 = softmax(Ab@W2) ----
__global__ void __launch_bounds__(512, 2) k_fused(
    const float* __restrict__ A, const uint4* __restrict__ Bf1, const uint4* __restrict__ Bf2,
    float* __restrict__ H1out, int nrows)
{
    extern __shared__ char smem[];
    float* Red = (float*)(smem + OFF_RED);
    int tid = threadIdx.x;
    int w16 = tid >> 5, lane = tid & 31;
    int mt = w16 >> 1, phase = w16 & 1;
    int ncBase = phase ? 7 : 0, ncN = phase ? 6 : 7;
    int g = lane >> 2, i2 = (lane & 3) * 2;
    int row0 = blockIdx.x * 128;

    stage_A<512>(smem, A, row0, nrows, tid);
    __syncthreads();

    uint32_t sb = smem_u32(smem);
    uint32_t aAddrHi = sb + OFF_AHI + (uint32_t)((16 * mt + (lane & 15)) * A_STRIDE) + ((lane >> 4) << 4);
    uint32_t aAddrLo = aAddrHi + (OFF_ALO - OFF_AHI);

    float acc[7][4];
    mainloop7(acc, Bf1, aAddrHi, aAddrLo, lane, ncBase, ncN);
    __syncthreads();   // all A reads done before overwrite

    int rLocA = 16 * mt + g, rLocB = rLocA + 8;
    int rA = row0 + rLocA, rB = row0 + rLocB;
    // residual reconstructed from smem (hi+lo); pads reconstruct to 0 -> stay 0
#pragma unroll
    for (int j = 0; j < 7; j++) {
        int col = (ncBase + j) * 8 + i2;
        if (j < ncN) {
            uint32_t* pHA = (uint32_t*)(smem + OFF_AHI + rLocA * A_STRIDE + col * 2);
            uint32_t* pLA = (uint32_t*)(smem + OFF_ALO + rLocA * A_STRIDE + col * 2);
            uint32_t* pHB = (uint32_t*)(smem + OFF_AHI + rLocB * A_STRIDE + col * 2);
            uint32_t* pLB = (uint32_t*)(smem + OFF_ALO + rLocB * A_STRIDE + col * 2);
            uint32_t hA = *pHA, lA = *pLA, hB = *pHB, lB = *pLB;
            float vA0 = fmaxf(acc[j][0] + recon2(hA, lA, 0), 0.f);
            float vA1 = fmaxf(acc[j][1] + recon2(hA, lA, 1), 0.f);
            float vB0 = fmaxf(acc[j][2] + recon2(hB, lB, 0), 0.f);
            float vB1 = fmaxf(acc[j][3] + recon2(hB, lB, 1), 0.f);
            uint32_t h, l;
            split2(vA0, vA1, h, l);
            *pHA = h; *pLA = l;
            split2(vB0, vB1, h, l);
            *pHB = h; *pLB = l;
        }
    }
    __syncthreads();

    mainloop7(acc, Bf2, aAddrHi, aAddrLo, lane, ncBase, ncN);

    // softmax epilogue (cross-phase reductions via smem)
    float mA = -1e30f, mB = -1e30f;
#pragma unroll
    for (int j = 0; j < 7; j++) {
        int col = (ncBase + j) * 8 + i2;
        if (j < ncN && col < 100) {
            mA = fmaxf(mA, fmaxf(acc[j][0], acc[j][1]));
            mB = fmaxf(mB, fmaxf(acc[j][2], acc[j][3]));
        }
    }
    phase_red(mA, mB, Red, mt, phase, g, lane, true);
    float sA = 0.f, sB = 0.f;
#pragma unroll
    for (int j = 0; j < 7; j++) {
        int col = (ncBase + j) * 8 + i2;
        if (j < ncN && col < 100) {
            acc[j][0] = __expf(acc[j][0] - mA);
            acc[j][1] = __expf(acc[j][1] - mA);
            acc[j][2] = __expf(acc[j][2] - mB);
            acc[j][3] = __expf(acc[j][3] - mB);
            sA += acc[j][0] + acc[j][1];
            sB += acc[j][2] + acc[j][3];
        }
    }
    phase_red(sA, sB, Red, mt, phase, g, lane, false);
    float iA = 1.f / sA, iB = 1.f / sB;
#pragma unroll
    for (int j = 0; j < 7; j++) {
        int col = (ncBase + j) * 8 + i2;
        if (j < ncN && col < 100) {
            if (rA < nrows)
                *(float2*)(H1out + (size_t)rA * 100 + col) =
                    make_float2(acc[j][0] * iA, acc[j][1] * iA);
            if (rB < nrows)
                *(float2*)(H1out + (size_t)rB * 100 + col) =
                    make_float2(acc[j][2] * iB, acc[j][3] * iB);
        }
    }
}

// ======================= h = H1^T @ X via mma (ldmatrix.trans) =======================
#define OC_XHI 0
#define OC_XLO 15360
#define OC_HHI 30720
#define OC_HLO 46080
#define SMEM_OUT 61440
#define OUTER_GRID 444

__global__ void __launch_bounds__(224) k_outer_mma(const float* __restrict__ H1,
                                                   const float* __restrict__ X,
                                                   float* __restrict__ hout) {
    extern __shared__ char smem[];
    int tid = threadIdx.x;
    int w = tid >> 5, lane = tid & 31;
    int g = lane >> 2, i2 = (lane & 3) * 2;

    for (int i = tid; i < 64 * 6 * 4; i += 224) {
        int t = i / (64 * 6), r = (i / 6) % 64, u = i % 6;
        *(uint32_t*)(smem + t * 15360 + r * 240 + 200 + u * 4) = 0u;
    }

    float acc[13][4];
#pragma unroll
    for (int nc = 0; nc < 13; nc++)
#pragma unroll
        for (int q = 0; q < 4; q++) acc[nc][q] = 0.f;

    uint32_t sb = smem_u32(smem);
    uint32_t aRow = (uint32_t)((lane & 7) + ((lane >> 4) << 3));
    uint32_t aAddrHi = sb + OC_HHI + aRow * 240 + (uint32_t)(((lane >> 3) & 1) << 4) + (uint32_t)(w * 32);
    uint32_t aAddrLo = aAddrHi + (OC_HLO - OC_HHI);
    uint32_t bRow = (uint32_t)((lane & 7) + (((lane >> 3) & 1) << 3));
    uint32_t bAddrHi = sb + OC_XHI + bRow * 240 + (uint32_t)((lane >> 4) << 4);
    uint32_t bAddrLo = bAddrHi + (OC_XLO - OC_XHI);

    const int nch = (NN + 63) / 64;
    for (int ch = blockIdx.x; ch < nch; ch += OUTER_GRID) {
        int base = ch * 64;
        bool tail = (base + 64 > NN);
        __syncthreads();
        if (tail) {
            for (int i = tid; i < SMEM_OUT / 16; i += 224)
                ((int4*)smem)[i] = make_int4(0, 0, 0, 0);
            __syncthreads();
        }
        for (int idx = tid; idx < 64 * 25; idx += 224) {
            int r = idx / 25, q = idx % 25;
            int node = base + r;
            if (node < NN) {
                uint32_t off = (uint32_t)(r * 240 + q * 8);
                float4 v = *(const float4*)(X + (size_t)node * 100 + q * 4);
                uint32_t h0, l0, h1, l1;
                split2(v.x, v.y, h0, l0);
                split2(v.z, v.w, h1, l1);
                *(uint2*)(smem + OC_XHI + off) = make_uint2(h0, h1);
                *(uint2*)(smem + OC_XLO + off) = make_uint2(l0, l1);
                float4 u = *(const float4*)(H1 + (size_t)node * 100 + q * 4);
                split2(u.x, u.y, h0, l0);
                split2(u.z, u.w, h1, l1);
                *(uint2*)(smem + OC_HHI + off) = make_uint2(h0, h1);
                *(uint2*)(smem + OC_HLO + off) = make_uint2(l0, l1);
            }
        }
        __syncthreads();

#pragma unroll
        for (int ks = 0; ks < 4; ks++) {
            uint32_t ah0, ah1, ah2, ah3, al0, al1, al2, al3;
            ldsm_x4t(ah0, ah1, ah2, ah3, aAddrHi + (uint32_t)(ks * 16 * 240));
            ldsm_x4t(al0, al1, al2, al3, aAddrLo + (uint32_t)(ks * 16 * 240));
#pragma unroll
            for (int c3 = 0; c3 < 7; c3++) {
                uint32_t bh0, bh1, bh2, bh3, bl0, bl1, bl2, bl3;
                ldsm_x4t(bh0, bh1, bh2, bh3, bAddrHi + (uint32_t)(ks * 16 * 240 + c3 * 32));
                ldsm_x4t(bl0, bl1, bl2, bl3, bAddrLo + (uint32_t)(ks * 16 * 240 + c3 * 32));
                int nc = 2 * c3;
                mma16816(acc[nc], ah0, ah1, ah2, ah3, bh0, bh1);
                mma16816(acc[nc], ah0, ah1, ah2, ah3, bl0, bl1);
                mma16816(acc[nc], al0, al1, al2, al3, bh0, bh1);
                if (c3 < 6) {
                    mma16816(acc[nc + 1], ah0, ah1, ah2, ah3, bh2, bh3);
                    mma16816(acc[nc + 1], ah0, ah1, ah2, ah3, bl2, bl3);
                    mma16816(acc[nc + 1], al0, al1, al2, al3, bh2, bh3);
                }
            }
        }
    }

    int kkA = 16 * w + g;
    int kkB = kkA + 8;
#pragma unroll
    for (int nc = 0; nc < 13; nc++) {
        int col = nc * 8 + i2;
        if (col < 100) {
            if (kkA < 100) {
                atomicAdd(&hout[kkA * 100 + col],     acc[nc][0]);
                atomicAdd(&hout[kkA * 100 + col + 1], acc[nc][1]);
            }
            if (kkB < 100) {
                atomicAdd(&hout[kkB * 100 + col],     acc[nc][2]);
                atomicAdd(&hout[kkB * 100 + col + 1], acc[nc][3]);
            }
        }
    }
}

// ---------------- final output (defers fin/finh reconstruction) ----------------
__global__ void k_final(float* __restrict__ out, const float* __restrict__ emb, int out_n) {
    int i4 = blockIdx.x * blockDim.x + threadIdx.x;
    const int half4 = ND / 4;
    if (i4 < half4) {
        int row = (i4 * 4) / 100;
        float4 a = ((const float4*)emb)[i4];
#pragma unroll
        for (int l = 0; l < LL; l++) {
            float4 xv = ((const float4*)g_xl[l])[i4];
            float iv = g_inv2[l][row];
            a.x = fmaf(xv.x, iv, a.x);
            a.y = fmaf(xv.y, iv, a.y);
            a.z = fmaf(xv.z, iv, a.z);
            a.w = fmaf(xv.w, iv, a.w);
        }
        a.x *= 0.25f; a.y *= 0.25f; a.z *= 0.25f; a.w *= 0.25f;
        ((float4*)out)[i4] = a;
    } else if (i4 < 2 * half4) {
        int j4 = i4 - half4;
        int row = (j4 * 4) / 100;
        float4 a = make_float4(0.f, 0.f, 0.f, 0.f);
#pragma unroll
        for (int l = 0; l < LL; l++) {
            float4 xv = ((const float4*)g_xl[l])[j4];
            float4 sv = ((const float4*)g_xsl[l])[j4];
            float iv = g_inv1[l][row];
            a.x = fmaf(xv.x - sv.x, iv, a.x);
            a.y = fmaf(xv.y - sv.y, iv, a.y);
            a.z = fmaf(xv.z - sv.z, iv, a.z);
            a.w = fmaf(xv.w - sv.w, iv, a.w);
        }
        const float third = 1.0f / 3.0f;
        a.x *= third; a.y *= third; a.z *= third; a.w *= third;
        ((float4*)out)[i4] = a;
    }
}

// ---------------- launcher ----------------
extern "C" void kernel_launch(void* const* d_in, const int* in_sizes, int n_in,
                              void* d_out, int out_size) {
    const float* embedding = (const float*)d_in[0];
    // d_in[1] = adj : mathematically cancels (softmax row-sums = 1)
    const float* edge_vals = (const float*)d_in[2];
    const float* W_item    = (const float*)d_in[3];
    const float* W_i1      = (const float*)d_in[4];
    const float* W_i2      = (const float*)d_in[5];
    const int*   edge_rows = (const int*)d_in[6];
    const int*   edge_cols = (const int*)d_in[7];
    float* out = (float*)d_out;

    float *xl, *xsl, *H1, *hh, *inv1, *inv2;
    __half *th;
    cudaGetSymbolAddress((void**)&th,   g_th);
    cudaGetSymbolAddress((void**)&xl,   g_xl);
    cudaGetSymbolAddress((void**)&xsl,  g_xsl);
    cudaGetSymbolAddress((void**)&H1,   g_H1);
    cudaGetSymbolAddress((void**)&hh,   g_hh);
    cudaGetSymbolAddress((void**)&inv1, g_inv1);
    cudaGetSymbolAddress((void**)&inv2, g_inv2);
    int *cnt;
    cudaGetSymbolAddress((void**)&cnt, g_cnt);
    uint4 *bf;
    cudaGetSymbolAddress((void**)&bf, g_Bf);

    cudaFuncSetAttribute(k_mma<EPI_NONE>,  cudaFuncAttributeMaxDynamicSharedMemorySize, SMEM_MMA);
    cudaFuncSetAttribute(k_mma<EPI_FINAL>, cudaFuncAttributeMaxDynamicSharedMemorySize, SMEM_MMA);
    cudaFuncSetAttribute(k_fused,          cudaFuncAttributeMaxDynamicSharedMemorySize, SMEM_MMA);
    cudaFuncSetAttribute(k_outer_mma,      cudaFuncAttributeMaxDynamicSharedMemorySize, SMEM_OUT);

    // side stream + fork/join events (created once; host-side resources only)
    static cudaStream_t s2 = nullptr;
    static cudaEvent_t evFork = nullptr, evJoin = nullptr;
    if (s2 == nullptr) {
        cudaStreamCreateWithFlags(&s2, cudaStreamNonBlocking);
        cudaEventCreateWithFlags(&evFork, cudaEventDisableTiming);
        cudaEventCreateWithFlags(&evJoin, cudaEventDisableTiming);
    }

    const int GB = (NN + 127) / 128;   // 782
    auto BF = [&](int s) { return bf + (size_t)s * 2912; };

    // fork: CSR build + zeroing on s2, weight prep + first GEMM on main
    cudaEventRecord(evFork, 0);
    cudaStreamWaitEvent(s2, evFork, 0);

    k_prep5<<<5, 256>>>(W_item, W_i1, W_i2);                                                   // main
    k_zeroi<<<(NN + 255) / 256, 256, 0, s2>>>(cnt, NN);                                        // s2
    k_zerof<<<(LL * KD + 255) / 256, 256, 0, s2>>>(hh, LL * KD);                               // s2
    k_mma<EPI_NONE><<<GB, 512, SMEM_MMA>>>(embedding, BF(0), nullptr, nullptr, th,
                                           nullptr, nullptr, NN);                              // main (ncu control)
    k_hist<<<1024, 256, 0, s2>>>(edge_rows);                                                   // s2
    k_scan1<<<NB_SCAN, 1024, 0, s2>>>();                                                       // s2
    k_scan2<<<1, 1, 0, s2>>>();                                                                // s2
    k_scan3<<<(NN + 255) / 256, 256, 0, s2>>>();                                               // s2
    k_scatter<<<1024, 256, 0, s2>>>(edge_rows, edge_cols, edge_vals);                          // s2
    cudaEventRecord(evJoin, s2);
    cudaStreamWaitEvent(0, evJoin, 0);

    const float* xin = embedding;
    for (int layer = 0; layer < LL; layer++) {
        float* xs_l = xsl + (size_t)layer * ND;
        float* x_l  = xl  + (size_t)layer * ND;
        float* h_l  = hh  + (size_t)layer * KD;
        if (layer > 0)
            k_mma<EPI_NONE><<<GB, 512, SMEM_MMA>>>(xin, BF(layer), nullptr, nullptr, th,
                                                   nullptr, nullptr, NN);
        k_spmm<<<(NN * 32 + 255) / 256, 256>>>(th, xs_l);
        k_fused<<<GB, 512, SMEM_MMA>>>(xs_l, BF(3), BF(4), H1, NN);
        k_outer_mma<<<OUTER_GRID, 224, SMEM_OUT>>>(H1, xs_l, h_l);
        k_preph<<<6, 512>>>(h_l);
        k_mma<EPI_FINAL><<<GB, 512, SMEM_MMA>>>(H1, BF(5), xs_l, x_l, nullptr,
                                                inv1 + (size_t)layer * NN,
                                                inv2 + (size_t)layer * NN, NN);
        xin = x_l;
    }

    k_final<<<(ND / 2 + 255) / 256, 256>>>(out, embedding, out_size);
}